// round 9
// baseline (speedup 1.0000x reference)
#include <cuda_runtime.h>
#include <math.h>

#define BB 8192
#define NN 4096
#define WBINS 1000
#define LSTRIDE 101        // L_CUTOFF + 1, row stride of sine_terms
#define LL 12              // truncated series: for sigma>0.6, term l=12 < 1e-9 rel
#define GRAD_GAUSS_THRES 0.6f
#define GPB 8              // batches per block
#define THREADS 512
#define SINE_STRIDE 1024   // padded row stride of g_sineT (zeros beyond WBINS)
#define TABROW 1002        // floats per table row (1001 used)

__device__ float g_sineT[LL * SINE_STRIDE];

// ---------------------------------------------------------------------------
// Kernel 0: transpose first LL columns of sine_terms, zero-pad to stride 1024
// ---------------------------------------------------------------------------
__global__ void transpose_kernel(const float* __restrict__ sine_terms) {
    int idx = blockIdx.x * blockDim.x + threadIdx.x;   // 0 .. LL*1024-1
    int l = idx >> 10;
    int w = idx & (SINE_STRIDE - 1);
    g_sineT[idx] = (w < WBINS) ? sine_terms[w * LSTRIDE + l] : 0.0f;
}

// ---------------------------------------------------------------------------
// Fused kernel. Per block: build 8 batches' single-float v-tables in SMEM,
//   u[idx] = pdf_pad[idx] * bw / (pdf_pad[idx+1] - pdf_pad[idx])   ( = left/grad )
//   v[idx] = u[idx] - (idx + 0.5) * bw                 (center folded in)
// from the truncated Legendre series (unnormalized pdf — normalization cancels),
// then evaluate 8*4096 omegas as  out = 1 / (v[idx] + w)
// == reference's grad_pdf / pdf_accurate. grad==0 -> v=inf -> out=0 (matches).
// pdf_pad = [pdf[0], pdf[0..999], pdf[998]].
// idx = floor(fma(w, inv_bw, 0.5)) <= 1000 always (w < pi_fp32), no clamp.
// ---------------------------------------------------------------------------
__global__ __launch_bounds__(THREADS, 4)
void fused_kernel(const float* __restrict__ sigmas,
                  const float* __restrict__ omegas,
                  const float* __restrict__ omega_grid,
                  float* __restrict__ out) {
    __shared__ float  s_tab[GPB][TABROW];            // ~32 KB
    __shared__ __align__(16) float s_expT[LL][GPB];  // transposed series weights
    __shared__ float  s_edge[16][4];                 // per-warp boundary pdf values
    __shared__ float2 s_par[GPB];

    const int tid  = threadIdx.x;
    const int lane = tid & 31;
    const int wid  = tid >> 5;
    const int base = blockIdx.x * GPB;

    const float bw     = __ldg(&omega_grid[1]) - __ldg(&omega_grid[0]);
    const float inv_bw = 1.0f / bw;

    // ---- phase 1: per-batch params + series weights -------------------------
    if (tid < GPB) {
        float sg = sigmas[base + tid];
        s_par[tid] = make_float2(-1.0f / (sg * sg),
                                 (sg > GRAD_GAUSS_THRES) ? 1.0f : 0.0f);
    }
    if (tid < GPB * LL) {
        int l = tid >> 3;
        int g = tid & (GPB - 1);
        float sg = sigmas[base + g];
        s_expT[l][g] = expf(-0.5f * (float)(l * (l + 1)) * (sg * sg));
    }
    __syncthreads();

    // ---- phase 2: series, two passes of 4 batches (regs <= 32) --------------
    const float c1 = ((float)(2 * tid + 1) + 0.5f) * bw;   // center of entry 2t+1
    const float c2 = ((float)(2 * tid + 2) + 0.5f) * bw;   // center of entry 2t+2

    #pragma unroll 1
    for (int half = 0; half < 2; half++) {
        const int gb = half * 4;
        float a0[4], a1[4];
        #pragma unroll
        for (int g = 0; g < 4; g++) { a0[g] = 0.0f; a1[g] = 0.0f; }

        #pragma unroll
        for (int l = LL - 1; l >= 0; l--) {   // small terms first
            float2 sv = *reinterpret_cast<const float2*>(
                            &g_sineT[l * SINE_STRIDE + 2 * tid]);
            float4 ev = *reinterpret_cast<const float4*>(&s_expT[l][gb]);
            a0[0] = fmaf(ev.x, sv.x, a0[0]);  a1[0] = fmaf(ev.x, sv.y, a1[0]);
            a0[1] = fmaf(ev.y, sv.x, a0[1]);  a1[1] = fmaf(ev.y, sv.y, a1[1]);
            a0[2] = fmaf(ev.z, sv.x, a0[2]);  a1[2] = fmaf(ev.z, sv.y, a1[2]);
            a0[3] = fmaf(ev.w, sv.x, a0[3]);  a1[3] = fmaf(ev.w, sv.y, a1[3]);
        }

        if (lane == 0) {
            #pragma unroll
            for (int g = 0; g < 4; g++) s_edge[wid][g] = a0[g];
        }
        __syncthreads();

        // n0[g] = pdf[2t+2]; t=499 overrides per pdf_pad[1001]=pdf[998]
        float n0[4];
        #pragma unroll
        for (int g = 0; g < 4; g++)
            n0[g] = __shfl_down_sync(0xffffffffu, a0[g], 1);
        if (lane == 31 && wid < 15) {
            #pragma unroll
            for (int g = 0; g < 4; g++) n0[g] = s_edge[wid + 1][g];
        }
        if (tid == WBINS / 2 - 1) {
            #pragma unroll
            for (int g = 0; g < 4; g++) n0[g] = a0[g];
        }

        if (tid < WBINS / 2) {
            #pragma unroll
            for (int g = 0; g < 4; g++) {
                float u1 = __fdiv_rn(a0[g] * bw, a1[g] - a0[g]);
                float u2 = __fdiv_rn(a1[g] * bw, n0[g] - a1[g]);
                s_tab[gb + g][2 * tid + 1] = u1 - c1;
                s_tab[gb + g][2 * tid + 2] = u2 - c2;
                if (tid == 0) s_tab[gb + g][0] = __int_as_float(0x7f800000);
            }
        }
        __syncthreads();   // also protects s_edge reuse next pass
    }

    // ---- phase 3: depth-2 software-pipelined evaluation ----------------------
    // Flat 16-chunk loop: chunk j covers elements [j*512, (j+1)*512) float4s of
    // this block's 8 rows; bl = j>>1 is warp-uniform (NN/4 == 2*THREADS).
    const float4* om4  = reinterpret_cast<const float4*>(omegas)
                         + (size_t)blockIdx.x * (GPB * NN / 4);
    float4*       out4 = reinterpret_cast<float4*>(out)
                         + (size_t)blockIdx.x * (GPB * NN / 4);
    const int NCHUNK = GPB * NN / 4 / THREADS;       // 16

    float4 buf0 = __ldcs(om4 + tid);
    float4 buf1 = __ldcs(om4 + THREADS + tid);

    #pragma unroll 1
    for (int j = 0; j < NCHUNK; j++) {
        float4 om = buf0;
        buf0 = buf1;
        if (j + 2 < NCHUNK)
            buf1 = __ldcs(om4 + (j + 2) * THREADS + tid);

        const int bl = j >> 1;
        float2 p = s_par[bl];
        float4 r;
        if (p.y > 0.5f) {
            const float* row = s_tab[bl];
            #pragma unroll
            for (int c = 0; c < 4; c++) {
                float w = (&om.x)[c];
                int idx = __float2int_rd(fmaf(w, inv_bw, 0.5f));
                (&r.x)[c] = __fdividef(1.0f, row[idx] + w);
            }
        } else {
            r.x = om.x * p.x; r.y = om.y * p.x;
            r.z = om.z * p.x; r.w = om.w * p.x;
        }
        __stcs(out4 + j * THREADS + tid, r);
    }
}

// ---------------------------------------------------------------------------
extern "C" void kernel_launch(void* const* d_in, const int* in_sizes, int n_in,
                              void* d_out, int out_size) {
    const float* sigmas     = (const float*)d_in[0];   // [B]
    const float* omegas     = (const float*)d_in[1];   // [B, N]
    const float* omega_grid = (const float*)d_in[2];   // [WBINS]
    const float* sine_terms = (const float*)d_in[4];   // [WBINS, 101]

    transpose_kernel<<<LL * SINE_STRIDE / 256, 256>>>(sine_terms);
    fused_kernel<<<BB / GPB, THREADS>>>(sigmas, omegas, omega_grid, (float*)d_out);
}

// round 10
// speedup vs baseline: 1.0660x; 1.0660x over previous
#include <cuda_runtime.h>
#include <math.h>

#define BB 8192
#define NN 4096
#define WBINS 1000
#define LSTRIDE 101        // L_CUTOFF + 1, row stride of sine_terms
#define LL 12              // truncated series: for sigma>0.6, term l=12 < 1e-9 rel
#define GRAD_GAUSS_THRES 0.6f
#define GPB 4              // batches per block
#define THREADS 256
#define SINE_STRIDE 1024   // padded row stride of g_sineT (zeros beyond WBINS)
#define TABROW 1002        // floats per table row (1001 used)

__device__ float g_sineT[LL * SINE_STRIDE];

// ---------------------------------------------------------------------------
// Kernel 0: transpose first LL columns of sine_terms.
// Coalesced reads over the row-major [WBINS,101] input; scattered writes
// (fire-and-forget). First 12*24 threads of block 0 zero the w>=1000 padding.
// ---------------------------------------------------------------------------
__global__ void transpose_kernel(const float* __restrict__ sine_terms) {
    int idx = blockIdx.x * blockDim.x + threadIdx.x;
    if (blockIdx.x == 0 && threadIdx.x < LL * (SINE_STRIDE - WBINS)) {
        int l = threadIdx.x / (SINE_STRIDE - WBINS);
        int w = WBINS + threadIdx.x % (SINE_STRIDE - WBINS);
        g_sineT[l * SINE_STRIDE + w] = 0.0f;
    }
    if (idx < WBINS * LSTRIDE) {
        int w = idx / LSTRIDE;
        int l = idx - w * LSTRIDE;
        if (l < LL) g_sineT[l * SINE_STRIDE + w] = sine_terms[idx];
    }
}

// ---------------------------------------------------------------------------
// Fused kernel. Per block: build 4 batches' single-float v-tables in SMEM,
//   u[idx] = pdf_pad[idx] * bw / (pdf_pad[idx+1] - pdf_pad[idx])   ( = left/grad )
//   v[idx] = u[idx] - (idx + 0.5) * bw                 (center folded in)
// from the truncated Legendre series (unnormalized pdf — normalization cancels),
// then evaluate 4*4096 omegas as  out = 1 / (v[idx] + w)
// == reference's grad_pdf / pdf_accurate. grad==0 -> v=inf -> out=0 (matches).
// pdf_pad = [pdf[0], pdf[0..999], pdf[998]].
// idx = floor(fma(w, inv_bw, 0.5)) <= 1000 always (w < pi_fp32), no clamp.
// Thread t (<250) owns bins 4t..4t+3, writes table entries 4t+1..4t+4.
// ---------------------------------------------------------------------------
__global__ __launch_bounds__(THREADS, 8)
void fused_kernel(const float* __restrict__ sigmas,
                  const float* __restrict__ omegas,
                  const float* __restrict__ omega_grid,
                  float* __restrict__ out) {
    __shared__ float  s_tab[GPB][TABROW];            // ~16 KB
    __shared__ __align__(16) float s_expT[LL][GPB];  // transposed series weights
    __shared__ float  s_edge[8][2];                  // per-warp boundary pdf values
    __shared__ float2 s_par[GPB];

    const int tid  = threadIdx.x;
    const int lane = tid & 31;
    const int wid  = tid >> 5;
    const int base = blockIdx.x * GPB;

    const float bw     = __ldg(&omega_grid[1]) - __ldg(&omega_grid[0]);
    const float inv_bw = 1.0f / bw;

    // ---- phase 1: per-batch params + series weights -------------------------
    if (tid < GPB) {
        float sg = sigmas[base + tid];
        s_par[tid] = make_float2(-1.0f / (sg * sg),
                                 (sg > GRAD_GAUSS_THRES) ? 1.0f : 0.0f);
    }
    if (tid < GPB * LL) {
        int l = tid >> 2;
        int g = tid & (GPB - 1);
        float sg = sigmas[base + g];
        s_expT[l][g] = expf(-0.5f * (float)(l * (l + 1)) * (sg * sg));
    }
    __syncthreads();

    // ---- phase 2: series, two passes of 2 batches (regs <= 32) --------------
    #pragma unroll 1
    for (int half = 0; half < 2; half++) {
        const int gb = half * 2;
        float A0[2], A1[2], A2[2], A3[2];     // bins 4t..4t+3 for 2 batches
        #pragma unroll
        for (int g = 0; g < 2; g++) { A0[g]=0.f; A1[g]=0.f; A2[g]=0.f; A3[g]=0.f; }

        #pragma unroll
        for (int l = LL - 1; l >= 0; l--) {   // small terms first
            float4 sv = *reinterpret_cast<const float4*>(
                            &g_sineT[l * SINE_STRIDE + 4 * tid]);
            float2 ev = *reinterpret_cast<const float2*>(&s_expT[l][gb]);
            A0[0] = fmaf(ev.x, sv.x, A0[0]);  A0[1] = fmaf(ev.y, sv.x, A0[1]);
            A1[0] = fmaf(ev.x, sv.y, A1[0]);  A1[1] = fmaf(ev.y, sv.y, A1[1]);
            A2[0] = fmaf(ev.x, sv.z, A2[0]);  A2[1] = fmaf(ev.y, sv.z, A2[1]);
            A3[0] = fmaf(ev.x, sv.w, A3[0]);  A3[1] = fmaf(ev.y, sv.w, A3[1]);
        }

        // warp w lane 0 holds pdf[128w] in A0
        if (lane == 0) {
            s_edge[wid][0] = A0[0];
            s_edge[wid][1] = A0[1];
        }
        __syncthreads();

        // n0[g] = pdf[4t+4]; t=249 overrides: entry 1000 right = pdf[998] = A2
        float n0[2];
        #pragma unroll
        for (int g = 0; g < 2; g++)
            n0[g] = __shfl_down_sync(0xffffffffu, A0[g], 1);
        if (lane == 31 && wid < 7) {
            n0[0] = s_edge[wid + 1][0];
            n0[1] = s_edge[wid + 1][1];
        }
        if (tid == 249) { n0[0] = A2[0]; n0[1] = A2[1]; }

        if (tid < 250) {
            #pragma unroll
            for (int g = 0; g < 2; g++) {
                float* trow = s_tab[gb + g];
                float e = 4.0f * (float)tid;
                trow[4*tid+1] = __fdiv_rn(A0[g]*bw, A1[g]-A0[g]) - (e+1.5f)*bw;
                trow[4*tid+2] = __fdiv_rn(A1[g]*bw, A2[g]-A1[g]) - (e+2.5f)*bw;
                trow[4*tid+3] = __fdiv_rn(A2[g]*bw, A3[g]-A2[g]) - (e+3.5f)*bw;
                trow[4*tid+4] = __fdiv_rn(A3[g]*bw, n0[g]-A3[g]) - (e+4.5f)*bw;
                if (tid == 0) trow[0] = __int_as_float(0x7f800000);
            }
        }
        __syncthreads();   // also protects s_edge reuse next pass
    }

    // ---- phase 3: per row, 4 chunks' LDGs issued up front (MLP=4) -----------
    const float4* om4  = reinterpret_cast<const float4*>(omegas)
                         + (size_t)blockIdx.x * (GPB * NN / 4);
    float4*       out4 = reinterpret_cast<float4*>(out)
                         + (size_t)blockIdx.x * (GPB * NN / 4);

    #pragma unroll 1
    for (int bl = 0; bl < GPB; bl++) {
        const int i0 = bl * (NN / 4) + tid;            // NN/4 = 1024 = 4*THREADS
        float2 p = s_par[bl];
        float4 m0 = __ldcs(om4 + i0);
        float4 m1 = __ldcs(om4 + i0 + THREADS);
        float4 m2 = __ldcs(om4 + i0 + 2 * THREADS);
        float4 m3 = __ldcs(om4 + i0 + 3 * THREADS);
        if (p.y > 0.5f) {
            const float* row = s_tab[bl];
            float4 r;
            #pragma unroll
            for (int q = 0; q < 4; q++) {
                float4 om = (q == 0) ? m0 : (q == 1) ? m1 : (q == 2) ? m2 : m3;
                #pragma unroll
                for (int c = 0; c < 4; c++) {
                    float w = (&om.x)[c];
                    int idx = __float2int_rd(fmaf(w, inv_bw, 0.5f));
                    (&r.x)[c] = __fdividef(1.0f, row[idx] + w);
                }
                __stcs(out4 + i0 + q * THREADS, r);
            }
        } else {
            float4 r;
            #pragma unroll
            for (int q = 0; q < 4; q++) {
                float4 om = (q == 0) ? m0 : (q == 1) ? m1 : (q == 2) ? m2 : m3;
                r.x = om.x * p.x; r.y = om.y * p.x;
                r.z = om.z * p.x; r.w = om.w * p.x;
                __stcs(out4 + i0 + q * THREADS, r);
            }
        }
    }
}

// ---------------------------------------------------------------------------
extern "C" void kernel_launch(void* const* d_in, const int* in_sizes, int n_in,
                              void* d_out, int out_size) {
    const float* sigmas     = (const float*)d_in[0];   // [B]
    const float* omegas     = (const float*)d_in[1];   // [B, N]
    const float* omega_grid = (const float*)d_in[2];   // [WBINS]
    const float* sine_terms = (const float*)d_in[4];   // [WBINS, 101]

    transpose_kernel<<<(WBINS * LSTRIDE + 255) / 256, 256>>>(sine_terms);
    fused_kernel<<<BB / GPB, THREADS>>>(sigmas, omegas, omega_grid, (float*)d_out);
}

// round 11
// speedup vs baseline: 1.1159x; 1.0468x over previous
#include <cuda_runtime.h>
#include <math.h>

#define BB 8192
#define NN 4096
#define WBINS 1000
#define LSTRIDE 101        // L_CUTOFF + 1, row stride of sine_terms
#define LL 12              // truncated series: for sigma>0.6, term l=12 < 1e-9 rel
#define GRAD_GAUSS_THRES 0.6f
#define GPB 4              // batches per block
#define THREADS 256
#define SINE_STRIDE 1024   // padded row stride of g_sineT (zeros beyond WBINS)
#define TABROW 1002        // floats per table row (1001 used)

__device__ float g_sineT[LL * SINE_STRIDE];

// ---------------------------------------------------------------------------
// Kernel 0: transpose first LL columns of sine_terms.
// Coalesced reads over the row-major [WBINS,101] input; scattered writes.
// First threads of block 0 zero the w>=1000 padding.
// ---------------------------------------------------------------------------
__global__ void transpose_kernel(const float* __restrict__ sine_terms) {
    int idx = blockIdx.x * blockDim.x + threadIdx.x;
    if (blockIdx.x == 0 && threadIdx.x < LL * (SINE_STRIDE - WBINS)) {
        int l = threadIdx.x / (SINE_STRIDE - WBINS);
        int w = WBINS + threadIdx.x % (SINE_STRIDE - WBINS);
        g_sineT[l * SINE_STRIDE + w] = 0.0f;
    }
    if (idx < WBINS * LSTRIDE) {
        int w = idx / LSTRIDE;
        int l = idx - w * LSTRIDE;
        if (l < LL) g_sineT[l * SINE_STRIDE + w] = sine_terms[idx];
    }
}

// ---------------------------------------------------------------------------
// Fused kernel. Per block: build 4 batches' single-float v-tables in SMEM,
//   u[idx] = pdf_pad[idx] * bw / (pdf_pad[idx+1] - pdf_pad[idx])   ( = left/grad )
//   v[idx] = u[idx] - (idx + 0.5) * bw                 (center folded in)
// from the truncated Legendre series (unnormalized pdf — normalization cancels),
// then evaluate 4*4096 omegas as  out = 1 / (v[idx] + w)
// == reference's grad_pdf / pdf_accurate. grad==0 -> v=inf -> out=0 (matches).
// pdf_pad = [pdf[0], pdf[0..999], pdf[998]].
// idx = floor(fma(w, inv_bw, 0.5)) <= 1000 always (w < pi_fp32), no clamp.
// Phase 2: SINGLE pass over batches; bins split into 2 segments of 500
// (thread handles bins 2j, 2j+1 with j = tid + 256*seg; j<500 stores).
// ---------------------------------------------------------------------------
__global__ __launch_bounds__(THREADS, 8)
void fused_kernel(const float* __restrict__ sigmas,
                  const float* __restrict__ omegas,
                  const float* __restrict__ omega_grid,
                  float* __restrict__ out) {
    __shared__ float  s_tab[GPB][TABROW];            // ~16 KB
    __shared__ __align__(16) float s_expT[LL][GPB];  // transposed series weights
    __shared__ float  s_edge[8][GPB];                // per-warp boundary pdf values
    __shared__ float  s_cross[GPB];                  // pdf[511] (segment boundary)
    __shared__ float2 s_par[GPB];

    const int tid  = threadIdx.x;
    const int lane = tid & 31;
    const int wid  = tid >> 5;
    const int base = blockIdx.x * GPB;

    const float bw     = __ldg(&omega_grid[1]) - __ldg(&omega_grid[0]);
    const float inv_bw = 1.0f / bw;

    // ---- phase 1: per-batch params + series weights -------------------------
    if (tid < GPB) {
        float sg = sigmas[base + tid];
        s_par[tid] = make_float2(-1.0f / (sg * sg),
                                 (sg > GRAD_GAUSS_THRES) ? 1.0f : 0.0f);
    }
    if (tid < GPB * LL) {
        int l = tid >> 2;
        int g = tid & (GPB - 1);
        float sg = sigmas[base + g];
        s_expT[l][g] = expf(-0.5f * (float)(l * (l + 1)) * (sg * sg));
    }
    __syncthreads();

    // ---- phase 2: series, single pass over 4 batches, 2 bin-segments --------
    #pragma unroll 1
    for (int seg = 0; seg < 2; seg++) {
        const int j = tid + 256 * seg;        // bin-pair index: bins 2j, 2j+1
        float a0[GPB], a1[GPB];
        #pragma unroll
        for (int g = 0; g < GPB; g++) { a0[g] = 0.0f; a1[g] = 0.0f; }

        #pragma unroll
        for (int l = LL - 1; l >= 0; l--) {   // small terms first
            float2 sv = *reinterpret_cast<const float2*>(
                            &g_sineT[l * SINE_STRIDE + 2 * j]);
            float4 ev = *reinterpret_cast<const float4*>(&s_expT[l][0]);
            a0[0] = fmaf(ev.x, sv.x, a0[0]);  a1[0] = fmaf(ev.x, sv.y, a1[0]);
            a0[1] = fmaf(ev.y, sv.x, a0[1]);  a1[1] = fmaf(ev.y, sv.y, a1[1]);
            a0[2] = fmaf(ev.z, sv.x, a0[2]);  a1[2] = fmaf(ev.z, sv.y, a1[2]);
            a0[3] = fmaf(ev.w, sv.x, a0[3]);  a1[3] = fmaf(ev.w, sv.y, a1[3]);
        }

        // warp w lane 0 holds pdf[2j] with j = 64w (+256*seg)
        if (lane == 0) {
            #pragma unroll
            for (int g = 0; g < GPB; g++) s_edge[wid][g] = a0[g];
        }
        if (seg == 0 && tid == 255) {          // pdf[511] for entry 512
            #pragma unroll
            for (int g = 0; g < GPB; g++) s_cross[g] = a1[g];
        }
        __syncthreads();

        // n0[g] = pdf[2j+2]
        float n0[GPB];
        #pragma unroll
        for (int g = 0; g < GPB; g++)
            n0[g] = __shfl_down_sync(0xffffffffu, a0[g], 1);
        if (lane == 31 && wid < 7) {
            #pragma unroll
            for (int g = 0; g < GPB; g++) n0[g] = s_edge[wid + 1][g];
        }
        if (j == 499) {                        // entry 1000 right = pdf[998] = a0
            #pragma unroll
            for (int g = 0; g < GPB; g++) n0[g] = a0[g];
        }

        const bool defer   = (seg == 0 && tid == 255);  // entry 512 done by seg1 tid0
        const bool active  = (j < 500);
        const float e = 2.0f * (float)j;

        #pragma unroll
        for (int g = 0; g < GPB; g++) {
            if (s_par[g].y > 0.5f) {
                float* trow = s_tab[g];
                if (active) {
                    trow[2*j+1] = __fdividef(a0[g]*bw, a1[g]-a0[g]) - (e+1.5f)*bw;
                    if (!defer)
                        trow[2*j+2] = __fdividef(a1[g]*bw, n0[g]-a1[g]) - (e+2.5f)*bw;
                }
                if (seg == 0 && tid == 0)
                    trow[0] = __int_as_float(0x7f800000);   // grad=0 -> +inf
                if (seg == 1 && tid == 0)                   // entry 512
                    trow[512] = __fdividef(s_cross[g]*bw, a0[g]-s_cross[g]) - 512.5f*bw;
            }
        }
        __syncthreads();   // protects s_edge/s_cross reuse + table visibility
    }

    // ---- phase 3: per row, 4 chunks' LDGs issued up front (MLP=4) -----------
    const float4* om4  = reinterpret_cast<const float4*>(omegas)
                         + (size_t)blockIdx.x * (GPB * NN / 4);
    float4*       out4 = reinterpret_cast<float4*>(out)
                         + (size_t)blockIdx.x * (GPB * NN / 4);

    #pragma unroll 1
    for (int bl = 0; bl < GPB; bl++) {
        const int i0 = bl * (NN / 4) + tid;            // NN/4 = 1024 = 4*THREADS
        float2 p = s_par[bl];
        float4 m0 = __ldcs(om4 + i0);
        float4 m1 = __ldcs(om4 + i0 + THREADS);
        float4 m2 = __ldcs(om4 + i0 + 2 * THREADS);
        float4 m3 = __ldcs(om4 + i0 + 3 * THREADS);
        if (p.y > 0.5f) {
            const float* row = s_tab[bl];
            float4 r;
            #pragma unroll
            for (int q = 0; q < 4; q++) {
                float4 om = (q == 0) ? m0 : (q == 1) ? m1 : (q == 2) ? m2 : m3;
                #pragma unroll
                for (int c = 0; c < 4; c++) {
                    float w = (&om.x)[c];
                    int idx = __float2int_rd(fmaf(w, inv_bw, 0.5f));
                    (&r.x)[c] = __fdividef(1.0f, row[idx] + w);
                }
                __stcs(out4 + i0 + q * THREADS, r);
            }
        } else {
            float4 r;
            #pragma unroll
            for (int q = 0; q < 4; q++) {
                float4 om = (q == 0) ? m0 : (q == 1) ? m1 : (q == 2) ? m2 : m3;
                r.x = om.x * p.x; r.y = om.y * p.x;
                r.z = om.z * p.x; r.w = om.w * p.x;
                __stcs(out4 + i0 + q * THREADS, r);
            }
        }
    }
}

// ---------------------------------------------------------------------------
extern "C" void kernel_launch(void* const* d_in, const int* in_sizes, int n_in,
                              void* d_out, int out_size) {
    const float* sigmas     = (const float*)d_in[0];   // [B]
    const float* omegas     = (const float*)d_in[1];   // [B, N]
    const float* omega_grid = (const float*)d_in[2];   // [WBINS]
    const float* sine_terms = (const float*)d_in[4];   // [WBINS, 101]

    transpose_kernel<<<(WBINS * LSTRIDE + 255) / 256, 256>>>(sine_terms);
    fused_kernel<<<BB / GPB, THREADS>>>(sigmas, omegas, omega_grid, (float*)d_out);
}